// round 17
// baseline (speedup 1.0000x reference)
#include <cuda_runtime.h>
#include <cstdint>
#include <cstddef>

#define NN   100000
#define EE   1600000
#define DIN  165
#define DMID 82
#define DH   128
#define DG   64

// ---------------- scratch (static device globals) ---------------------------
__device__ float g_y1 [NN * DIN];    // boosted features
__device__ float g_zl [NN * DH];     // y1 @ sage_wl
__device__ float g_zr [NN * DH];     // y1 @ sage_wr
__device__ float g_x2 [NN * DH];     // SAGE output
__device__ float g_h  [NN * DG];     // GAT projected features
__device__ float g_as [NN];
__device__ float g_ad [NN];
__device__ int   g_cnt [NN];
__device__ int   g_rowptr[NN + 1];
__device__ int   g_cursor[NN];
__device__ int   g_bsum[256];
__device__ int   g_col [EE];

// ---------------- warp reduce helpers ---------------------------------------
__device__ __forceinline__ float wredmax(float v) {
    #pragma unroll
    for (int o = 16; o; o >>= 1) v = fmaxf(v, __shfl_xor_sync(0xffffffffu, v, o));
    return v;
}
__device__ __forceinline__ float wredsum(float v) {
    #pragma unroll
    for (int o = 16; o; o >>= 1) v += __shfl_xor_sync(0xffffffffu, v, o);
    return v;
}

// ---------------- CSR build --------------------------------------------------
__global__ void k_zero_cnt(int n) {
    int i = blockIdx.x * blockDim.x + threadIdx.x;
    if (i < n) g_cnt[i] = 0;
}

__global__ void k_hist(const int* __restrict__ ei, int e, int n) {
    int i = blockIdx.x * blockDim.x + threadIdx.x;
    if (i < e) {
        int d = ei[e + i];
        if ((unsigned)d < (unsigned)n) atomicAdd(&g_cnt[d], 1);
    }
}

__global__ void k_scan1(int n) {
    __shared__ int sh[1024];
    int t = threadIdx.x;
    int i = blockIdx.x * 1024 + t;
    int v = (i < n) ? g_cnt[i] : 0;
    sh[t] = v;
    __syncthreads();
    #pragma unroll
    for (int off = 1; off < 1024; off <<= 1) {
        int x = (t >= off) ? sh[t - off] : 0;
        __syncthreads();
        sh[t] += x;
        __syncthreads();
    }
    int incl = sh[t];
    if (i < n) g_rowptr[i] = incl - v;
    if (t == 1023) g_bsum[blockIdx.x] = incl;
}

__global__ void k_scan2(int nb) {
    __shared__ int sh[256];
    int t = threadIdx.x;
    int v = (t < nb) ? g_bsum[t] : 0;
    sh[t] = v;
    __syncthreads();
    #pragma unroll
    for (int off = 1; off < 256; off <<= 1) {
        int x = (t >= off) ? sh[t - off] : 0;
        __syncthreads();
        sh[t] += x;
        __syncthreads();
    }
    if (t < nb) g_bsum[t] = sh[t] - v;   // exclusive
}

__global__ void k_scan3(int n, int e) {
    int i = blockIdx.x * blockDim.x + threadIdx.x;
    if (i < n) {
        int v = g_rowptr[i] + g_bsum[i >> 10];
        g_rowptr[i] = v;
        g_cursor[i] = v;
    }
    if (i == 0) g_rowptr[n] = e;
}

__global__ void k_fill(const int* __restrict__ ei, int e, int n) {
    int i = blockIdx.x * blockDim.x + threadIdx.x;
    if (i < e) {
        int d = ei[e + i];
        int s = ei[i];
        if ((unsigned)d < (unsigned)n && (unsigned)s < (unsigned)n) {
            int pos = atomicAdd(&g_cursor[d], 1);
            g_col[pos] = s;
        }
    }
}

// ---------------- tiled SGEMM core: 64 rows x (NT*64) cols, 256 thr ---------
// Exact-K (full 32-chunks, templated tail). W fetched via functor.
template<int K, int NT, typename WF>
__device__ __forceinline__ void gemm_tile(
    const float* __restrict__ A, int n, int rowBase, int tid, WF wf,
    float (*sA)[33], float* sW, float (&acc)[NT][4][4])
{
    const int tx = tid & 15, ty = tid >> 4;
    constexpr int NFULL = K / 32;
    constexpr int TAIL  = K % 32;
    constexpr int WROW  = 64 * NT;

    #pragma unroll 1
    for (int ch = 0; ch < NFULL; ch++) {
        int k0 = ch * 32;
        #pragma unroll
        for (int i = 0; i < 8; i++) {
            int idx = tid + i * 256;
            int r = idx >> 5, kk = idx & 31;
            int row = rowBase + r;
            sA[r][kk] = (row < n) ? A[(size_t)row * K + k0 + kk] : 0.0f;
        }
        #pragma unroll
        for (int i = 0; i < 8 * NT; i++) {
            int idx = tid + i * 256;
            int kk = idx / WROW, c = idx % WROW;
            sW[kk * WROW + c] = wf(k0 + kk, c);
        }
        __syncthreads();
        #pragma unroll
        for (int kk = 0; kk < 32; kk++) {
            float a0 = sA[ty * 4 + 0][kk];
            float a1 = sA[ty * 4 + 1][kk];
            float a2 = sA[ty * 4 + 2][kk];
            float a3 = sA[ty * 4 + 3][kk];
            #pragma unroll
            for (int t = 0; t < NT; t++) {
                float4 b = *(const float4*)&sW[kk * WROW + t * 64 + tx * 4];
                acc[t][0][0] += a0 * b.x; acc[t][0][1] += a0 * b.y; acc[t][0][2] += a0 * b.z; acc[t][0][3] += a0 * b.w;
                acc[t][1][0] += a1 * b.x; acc[t][1][1] += a1 * b.y; acc[t][1][2] += a1 * b.z; acc[t][1][3] += a1 * b.w;
                acc[t][2][0] += a2 * b.x; acc[t][2][1] += a2 * b.y; acc[t][2][2] += a2 * b.z; acc[t][2][3] += a2 * b.w;
                acc[t][3][0] += a3 * b.x; acc[t][3][1] += a3 * b.y; acc[t][3][2] += a3 * b.z; acc[t][3][3] += a3 * b.w;
            }
        }
        __syncthreads();
    }

    if constexpr (TAIL > 0) {
        constexpr int k0 = NFULL * 32;
        for (int idx = tid; idx < 64 * TAIL; idx += 256) {
            int r = idx / TAIL, kk = idx % TAIL;
            int row = rowBase + r;
            sA[r][kk] = (row < n) ? A[(size_t)row * K + k0 + kk] : 0.0f;
        }
        for (int idx = tid; idx < TAIL * WROW; idx += 256) {
            int kk = idx / WROW, c = idx % WROW;
            sW[kk * WROW + c] = wf(k0 + kk, c);
        }
        __syncthreads();
        #pragma unroll
        for (int kk = 0; kk < TAIL; kk++) {
            float a0 = sA[ty * 4 + 0][kk];
            float a1 = sA[ty * 4 + 1][kk];
            float a2 = sA[ty * 4 + 2][kk];
            float a3 = sA[ty * 4 + 3][kk];
            #pragma unroll
            for (int t = 0; t < NT; t++) {
                float4 b = *(const float4*)&sW[kk * WROW + t * 64 + tx * 4];
                acc[t][0][0] += a0 * b.x; acc[t][0][1] += a0 * b.y; acc[t][0][2] += a0 * b.z; acc[t][0][3] += a0 * b.w;
                acc[t][1][0] += a1 * b.x; acc[t][1][1] += a1 * b.y; acc[t][1][2] += a1 * b.z; acc[t][1][3] += a1 * b.w;
                acc[t][2][0] += a2 * b.x; acc[t][2][1] += a2 * b.y; acc[t][2][2] += a2 * b.z; acc[t][2][3] += a2 * b.w;
                acc[t][3][0] += a3 * b.x; acc[t][3][1] += a3 * b.y; acc[t][3][2] += a3 * b.z; acc[t][3][3] += a3 * b.w;
            }
        }
        __syncthreads();
    }
}

// Stage-2 chunk for the fused FB kernel: A lives in smem (sT), W in sW.
template<int CSZ, int NT>
__device__ __forceinline__ void fb2_chunk(
    int k0, int colBase, const float* __restrict__ w2, int tid,
    float (*sT)[84], float* sW, float (&acc)[NT][4][4])
{
    const int tx = tid & 15, ty = tid >> 4;
    constexpr int WROW = 64 * NT;
    for (int idx = tid; idx < CSZ * WROW; idx += 256) {
        int kk = idx / WROW, c = idx % WROW;
        int col = colBase + c;
        sW[kk * WROW + c] = (col < DIN) ? w2[(size_t)(k0 + kk) * DIN + col] : 0.0f;
    }
    __syncthreads();
    #pragma unroll
    for (int kk = 0; kk < CSZ; kk++) {
        float a0 = sT[ty * 4 + 0][k0 + kk];
        float a1 = sT[ty * 4 + 1][k0 + kk];
        float a2 = sT[ty * 4 + 2][k0 + kk];
        float a3 = sT[ty * 4 + 3][k0 + kk];
        #pragma unroll
        for (int t = 0; t < NT; t++) {
            float4 b = *(const float4*)&sW[kk * WROW + t * 64 + tx * 4];
            acc[t][0][0] += a0 * b.x; acc[t][0][1] += a0 * b.y; acc[t][0][2] += a0 * b.z; acc[t][0][3] += a0 * b.w;
            acc[t][1][0] += a1 * b.x; acc[t][1][1] += a1 * b.y; acc[t][1][2] += a1 * b.z; acc[t][1][3] += a1 * b.w;
            acc[t][2][0] += a2 * b.x; acc[t][2][1] += a2 * b.y; acc[t][2][2] += a2 * b.z; acc[t][2][3] += a2 * b.w;
            acc[t][3][0] += a3 * b.x; acc[t][3][1] += a3 * b.y; acc[t][3][2] += a3 * b.z; acc[t][3][3] += a3 * b.w;
        }
    }
    __syncthreads();
}

// Fused FeatureBooster: T = relu(x@w1) in smem, then y1 = x * sigmoid(2*(T@w2)).
__global__ __launch_bounds__(256) void k_fbf(const float* __restrict__ x,
                                             const float* __restrict__ w1,
                                             const float* __restrict__ w2, int n)
{
    __shared__ float sA[64][33];
    __shared__ float sW[32 * 128];
    __shared__ float sT[64][84];
    int tid = threadIdx.x;
    int rowBase = blockIdx.y * 64;
    int tx = tid & 15, ty = tid >> 4;

    // ---- stage 1: T = relu(x @ w1), all 82 cols (NT=2 covers 128) ----
    {
        float acc[2][4][4] = {};
        auto wf = [&](int k, int c) -> float {
            return (c < DMID) ? w1[(size_t)k * DMID + c] : 0.0f;
        };
        gemm_tile<DIN, 2>(x, n, rowBase, tid, wf, sA, sW, acc);
        #pragma unroll
        for (int t = 0; t < 2; t++)
        #pragma unroll
        for (int i = 0; i < 4; i++) {
            #pragma unroll
            for (int j = 0; j < 4; j++) {
                int c = t * 64 + tx * 4 + j;
                if (c < DMID) sT[ty * 4 + i][c] = fmaxf(acc[t][i][j], 0.0f);
            }
        }
        __syncthreads();
    }

    // ---- stage 2: y1 = x * sigmoid(2 * (T @ w2)), K=82 ----
    // col tile 0: NT=2 (cols 0..127)
    {
        float acc[2][4][4] = {};
        fb2_chunk<32, 2>(0,  0, w2, tid, sT, sW, acc);
        fb2_chunk<32, 2>(32, 0, w2, tid, sT, sW, acc);
        fb2_chunk<18, 2>(64, 0, w2, tid, sT, sW, acc);
        #pragma unroll
        for (int t = 0; t < 2; t++)
        #pragma unroll
        for (int i = 0; i < 4; i++) {
            int r = rowBase + ty * 4 + i;
            if (r >= n) continue;
            #pragma unroll
            for (int j = 0; j < 4; j++) {
                int c = t * 64 + tx * 4 + j;
                float sig = 1.0f / (1.0f + __expf(-2.0f * acc[t][i][j]));
                g_y1[(size_t)r * DIN + c] = x[(size_t)r * DIN + c] * sig;
            }
        }
        __syncthreads();
    }
    // col tile 1: NT=1 (cols 128..164)
    {
        float acc[1][4][4] = {};
        fb2_chunk<32, 1>(0,  128, w2, tid, sT, sW, acc);
        fb2_chunk<32, 1>(32, 128, w2, tid, sT, sW, acc);
        fb2_chunk<18, 1>(64, 128, w2, tid, sT, sW, acc);
        #pragma unroll
        for (int i = 0; i < 4; i++) {
            int r = rowBase + ty * 4 + i;
            if (r >= n) continue;
            #pragma unroll
            for (int j = 0; j < 4; j++) {
                int c = 128 + tx * 4 + j;
                if (c < DIN) {
                    float sig = 1.0f / (1.0f + __expf(-2.0f * acc[0][i][j]));
                    g_y1[(size_t)r * DIN + c] = x[(size_t)r * DIN + c] * sig;
                }
            }
        }
    }
}

// SAGE dual GEMM, NT=4: one block computes zl (cols 0..127) and zr (128..255).
__global__ __launch_bounds__(256) void k_dual(const float* __restrict__ wl,
                                              const float* __restrict__ wr, int n)
{
    __shared__ float sA[64][33];
    __shared__ float sW[32 * 256];
    float acc[4][4][4] = {};
    int tid = threadIdx.x;
    int rowBase = blockIdx.y * 64;
    auto wf = [&](int k, int c) -> float {
        return (c < DH) ? wl[(size_t)k * DH + c] : wr[(size_t)k * DH + (c - DH)];
    };
    gemm_tile<DIN, 4>(g_y1, n, rowBase, tid, wf, sA, sW, acc);
    int tx = tid & 15, ty = tid >> 4;
    #pragma unroll
    for (int t = 0; t < 4; t++)
    #pragma unroll
    for (int i = 0; i < 4; i++) {
        int r = rowBase + ty * 4 + i;
        if (r >= n) continue;
        float* dst = (t < 2) ? g_zl : g_zr;
        int cb = (t & 1) * 64;
        #pragma unroll
        for (int j = 0; j < 4; j++) {
            int c = cb + tx * 4 + j;
            dst[(size_t)r * DH + c] = acc[t][i][j];
        }
    }
}

// SAGE finalize: x2 = relu(mean_gather(zl) + zr + bl)   (warp per node)
__global__ __launch_bounds__(256) void k_sage_fin(const float* __restrict__ bl, int n)
{
    int w = (blockIdx.x * blockDim.x + threadIdx.x) >> 5;
    int lane = threadIdx.x & 31;
    if (w >= n) return;
    int beg = g_rowptr[w], end = g_rowptr[w + 1];
    float4 acc = make_float4(0.f, 0.f, 0.f, 0.f);
    int e = beg;
    for (; e + 2 <= end; e += 2) {
        const float4* p0 = (const float4*)(g_zl + (size_t)g_col[e]     * DH);
        const float4* p1 = (const float4*)(g_zl + (size_t)g_col[e + 1] * DH);
        float4 a = p0[lane], b = p1[lane];
        acc.x += a.x + b.x; acc.y += a.y + b.y;
        acc.z += a.z + b.z; acc.w += a.w + b.w;
    }
    if (e < end) {
        const float4* p0 = (const float4*)(g_zl + (size_t)g_col[e] * DH);
        float4 a = p0[lane];
        acc.x += a.x; acc.y += a.y; acc.z += a.z; acc.w += a.w;
    }
    float inv = 1.0f / fmaxf((float)(end - beg), 1.0f);
    const float4* zr  = (const float4*)(g_zr + (size_t)w * DH);
    const float4* bl4 = (const float4*)bl;
    float4 z = zr[lane], b4 = bl4[lane];
    float4 o;
    o.x = fmaxf(acc.x * inv + z.x + b4.x, 0.0f);
    o.y = fmaxf(acc.y * inv + z.y + b4.y, 0.0f);
    o.z = fmaxf(acc.z * inv + z.z + b4.z, 0.0f);
    o.w = fmaxf(acc.w * inv + z.w + b4.w, 0.0f);
    ((float4*)(g_x2 + (size_t)w * DH))[lane] = o;
}

// GAT projection + attention logits fused: g_h = x2 @ gat_w; as/ad per row.
__global__ __launch_bounds__(256) void k_gat_h(const float* __restrict__ gw,
                                               const float* __restrict__ att_s,
                                               const float* __restrict__ att_d, int n)
{
    __shared__ float sA[64][33];
    __shared__ float sW[32 * 64];
    float acc[1][4][4] = {};
    int tid = threadIdx.x;
    int rowBase = blockIdx.y * 64;
    auto wf = [&](int k, int c) -> float { return gw[(size_t)k * DG + c]; };
    gemm_tile<DH, 1>(g_x2, n, rowBase, tid, wf, sA, sW, acc);
    int tx = tid & 15, ty = tid >> 4;
    #pragma unroll
    for (int i = 0; i < 4; i++) {
        int r = rowBase + ty * 4 + i;
        float ps = 0.0f, pd = 0.0f;
        #pragma unroll
        for (int j = 0; j < 4; j++) {
            int c = tx * 4 + j;
            if (r < n) g_h[(size_t)r * DG + c] = acc[0][i][j];
            ps += acc[0][i][j] * att_s[c];
            pd += acc[0][i][j] * att_d[c];
        }
        #pragma unroll
        for (int o = 8; o; o >>= 1) {
            ps += __shfl_xor_sync(0xffffffffu, ps, o);
            pd += __shfl_xor_sync(0xffffffffu, pd, o);
        }
        if (tx == 0 && r < n) { g_as[r] = ps; g_ad[r] = pd; }
    }
}

// GAT softmax-aggregate + bias + relu + Cheb(64->1) + sigmoid, fully fused.
__global__ __launch_bounds__(256) void k_gat_agg(const float* __restrict__ gat_b,
                                                 const float* __restrict__ cheb_w,
                                                 const float* __restrict__ cheb_b,
                                                 float* __restrict__ out, int n)
{
    int w = (blockIdx.x * blockDim.x + threadIdx.x) >> 5;
    int lane = threadIdx.x & 31;
    if (w >= n) return;
    int beg = g_rowptr[w], end = g_rowptr[w + 1];
    float ad_i = g_ad[w];
    float es = g_as[w] + ad_i;
    es = es > 0.0f ? es : 0.2f * es;            // self-loop leaky relu
    float m = es;
    for (int base = beg; base < end; base += 32) {
        int j = base + lane;
        float e = -1e30f;
        if (j < end) {
            int s = g_col[j];
            float t = g_as[s] + ad_i;
            e = t > 0.0f ? t : 0.2f * t;
        }
        m = fmaxf(m, e);
    }
    m = wredmax(m);
    float sl = 0.0f, a0 = 0.0f, a1 = 0.0f;
    for (int base = beg; base < end; base += 32) {
        int j = base + lane;
        int s = 0;
        float wgt = 0.0f;
        if (j < end) {
            s = g_col[j];
            float t = g_as[s] + ad_i;
            t = t > 0.0f ? t : 0.2f * t;
            wgt = __expf(t - m);
        }
        sl += wgt;
        int cnt = min(32, end - base);
        for (int jj = 0; jj < cnt; jj++) {
            float wj = __shfl_sync(0xffffffffu, wgt, jj);
            int   sj = __shfl_sync(0xffffffffu, s, jj);
            float2 hv = ((const float2*)(g_h + (size_t)sj * DG))[lane];
            a0 += wj * hv.x;
            a1 += wj * hv.y;
        }
    }
    float ws = __expf(es - m);
    float stot = wredsum(sl) + ws;
    float2 hi = ((const float2*)(g_h + (size_t)w * DG))[lane];
    a0 += ws * hi.x;
    a1 += ws * hi.y;
    float r = 1.0f / (stot + 1e-16f);
    float x0 = fmaxf(a0 * r + gat_b[2 * lane],     0.0f);
    float x1 = fmaxf(a1 * r + gat_b[2 * lane + 1], 0.0f);
    float part = x0 * cheb_w[2 * lane] + x1 * cheb_w[2 * lane + 1];
    part = wredsum(part);
    if (lane == 0) out[w] = 1.0f / (1.0f + __expf(-(part + cheb_b[0])));
}

// ---------------- launch -----------------------------------------------------
extern "C" void kernel_launch(void* const* d_in, const int* in_sizes, int n_in,
                              void* d_out, int out_size)
{
    const float* x       = (const float*)d_in[0];
    const int*   ei      = (const int*)d_in[1];       // int32
    const float* fb_w1   = (const float*)d_in[2];
    const float* fb_w2   = (const float*)d_in[3];
    const float* sage_wl = (const float*)d_in[4];
    const float* sage_bl = (const float*)d_in[5];
    const float* sage_wr = (const float*)d_in[6];
    const float* gat_w   = (const float*)d_in[7];
    const float* att_s   = (const float*)d_in[8];
    const float* att_d   = (const float*)d_in[9];
    const float* gat_b   = (const float*)d_in[10];
    const float* cheb_w  = (const float*)d_in[11];
    const float* cheb_b  = (const float*)d_in[12];
    float*       out     = (float*)d_out;

    int n = in_sizes[0] / DIN;
    int e = in_sizes[1] / 2;

    // side stream + events for the CSR branch
    static cudaStream_t s2 = nullptr;
    static cudaEvent_t ev0 = nullptr, ev1 = nullptr;
    if (!s2) {
        cudaStreamCreateWithFlags(&s2, cudaStreamNonBlocking);
        cudaEventCreateWithFlags(&ev0, cudaEventDisableTiming);
        cudaEventCreateWithFlags(&ev1, cudaEventDisableTiming);
    }

    // fork: CSR build on s2, concurrent with the FB/SAGE GEMM chain
    cudaEventRecord(ev0, 0);
    cudaStreamWaitEvent(s2, ev0, 0);
    k_zero_cnt<<<(n + 255) / 256, 256, 0, s2>>>(n);
    k_hist<<<(e + 255) / 256, 256, 0, s2>>>(ei, e, n);
    int nb = (n + 1023) / 1024;
    k_scan1<<<nb, 1024, 0, s2>>>(n);
    k_scan2<<<1, 256, 0, s2>>>(nb);
    k_scan3<<<(n + 255) / 256, 256, 0, s2>>>(n, e);
    k_fill<<<(e + 255) / 256, 256, 0, s2>>>(ei, e, n);
    cudaEventRecord(ev1, s2);

    int rowTiles = (n + 63) / 64;
    // FeatureBooster (fused fb1+fb2)
    { dim3 g(1, rowTiles); k_fbf<<<g, 256>>>(x, fb_w1, fb_w2, n); }
    // SAGE dual projection (NT=4)
    { dim3 g(1, rowTiles); k_dual<<<g, 256>>>(sage_wl, sage_wr, n); }

    // join: gathers need the CSR
    cudaStreamWaitEvent(0, ev1, 0);
    k_sage_fin<<<(n + 7) / 8, 256>>>(sage_bl, n);
    // GAT
    { dim3 g(1, rowTiles); k_gat_h<<<g, 256>>>(gat_w, att_s, att_d, n); }
    k_gat_agg<<<(n + 7) / 8, 256>>>(gat_b, cheb_w, cheb_b, out, n);
}